// round 12
// baseline (speedup 1.0000x reference)
// NodeContrastiveLoss — fused fp8(e4m3) mma.sync + streaming LSE, z1z1 triangle.
// R12: software-pipeline the exp2 epilogue one nbp behind the MMA stream
// (mma0,mma1,epi0,mma2,epi1,mma3,epi2,epi3 with 2 accumulator sets) so the
// per-tile barrier-aligned epilogue phases no longer starve the tensor pipe.
// Disambiguates fp8 rt: big win => rt16 (2x fp16); neutral => rt>=24 (wall).
#include <cuda_runtime.h>
#include <cuda_fp8.h>
#include <cstdint>
#include <cstddef>
#include <cmath>

#define N_ROWS 16384
#define DIM    128
#define NCTA   296
#define UNITS_A 16384        // z1*z2^T: 128 rt x 128 bt
#define UNITS_B 8256         // triangular z1*z1^T units (incl. diagonal)

#define INV_TAU 14.285714285714286f
#define K1F     20.609929155556620f    // log2(e)/tau
#define LN2F    0.6931471805599453f

static __device__ uint32_t g_f1[(size_t)N_ROWS * 32];   // e4m3 rows, 4 packed/word
static __device__ uint32_t g_f2[(size_t)N_ROWS * 32];
static __device__ float    g_pos[N_ROWS];
static __device__ float    g_rowsum[N_ROWS];
static __device__ float    g_bsum[128];

// ---------------- helpers ----------------
__device__ __forceinline__ uint32_t smem_u32(const void* p) {
    uint32_t r;
    asm("{ .reg .u64 t; cvta.to.shared.u64 t, %1; cvt.u32.u64 %0, t; }" : "=r"(r) : "l"(p));
    return r;
}
__device__ __forceinline__ void cp_async16(uint32_t dst, const void* src) {
    asm volatile("cp.async.cg.shared.global [%0], [%1], 16;" :: "r"(dst), "l"(src) : "memory");
}
__device__ __forceinline__ void cp_commit() { asm volatile("cp.async.commit_group;" ::: "memory"); }
template <int N>
__device__ __forceinline__ void cp_wait() { asm volatile("cp.async.wait_group %0;" :: "n"(N) : "memory"); }

__device__ __forceinline__ void ldsm4(uint32_t r[4], uint32_t addr) {
    asm volatile("ldmatrix.sync.aligned.m8n8.x4.shared.b16 {%0,%1,%2,%3}, [%4];"
                 : "=r"(r[0]), "=r"(r[1]), "=r"(r[2]), "=r"(r[3]) : "r"(addr));
}
// fp8 e4m3 mma: D,C f32x4; A 4 regs; B 2 regs (k32)
__device__ __forceinline__ void mmafp8(float c[4], const uint32_t a[4], uint32_t b0, uint32_t b1) {
    asm volatile(
        "mma.sync.aligned.m16n8k32.row.col.f32.e4m3.e4m3.f32 "
        "{%0,%1,%2,%3}, {%4,%5,%6,%7}, {%8,%9}, {%0,%1,%2,%3};"
        : "+f"(c[0]), "+f"(c[1]), "+f"(c[2]), "+f"(c[3])
        : "r"(a[0]), "r"(a[1]), "r"(a[2]), "r"(a[3]), "r"(b0), "r"(b1));
}
__device__ __forceinline__ float ex2f(float x) { float y; asm("ex2.approx.f32 %0, %1;" : "=f"(y) : "f"(x)); return y; }
__device__ __forceinline__ float lg2f(float x) { float y; asm("lg2.approx.f32 %0, %1;" : "=f"(y) : "f"(x)); return y; }

// fp8 tile: 128 rows x 128 B (8 chunks of 16 B), 3-bit XOR swizzle (R4-proven).
__device__ __forceinline__ uint32_t swz8(int row, int c) {
    return (uint32_t)(row * 128 + (((c ^ row) & 7) << 4));
}

// ---------------- SMEM layout (dynamic, 56 KB/CTA) ----------------
#define SMEM_A  0
#define SMEM_B(s) (16384 + (s) * 16384)   // 2 stages x 16 KB
#define SMEM_C  49152                     // 2 x 4 KB col-sum staging slots
#define SMEM_TOTAL 57344

// ---------------- kernel 1: normalize + e4m3 + exact pos ----------------
__device__ __forceinline__ float dot4(float4 a, float4 b) {
    return a.x * b.x + a.y * b.y + a.z * b.z + a.w * b.w;
}
__device__ __forceinline__ uint32_t pack_fp8(float4 v, float s) {
    __nv_fp8x2_storage_t lo = __nv_cvt_float2_to_fp8x2(make_float2(v.x * s, v.y * s),
                                                       __NV_SATFINITE, __NV_E4M3);
    __nv_fp8x2_storage_t hi = __nv_cvt_float2_to_fp8x2(make_float2(v.z * s, v.w * s),
                                                       __NV_SATFINITE, __NV_E4M3);
    return (uint32_t)lo | ((uint32_t)hi << 16);
}
__global__ void __launch_bounds__(256) norm_kernel(const float* __restrict__ z1,
                                                   const float* __restrict__ z2) {
    int gw = blockIdx.x * 8 + (threadIdx.x >> 5);
    int lane = threadIdx.x & 31;
    if (threadIdx.x < 8) g_rowsum[blockIdx.x * 8 + threadIdx.x] = 0.f;
    float4 v1 = ((const float4*)(z1 + (size_t)gw * DIM))[lane];
    float4 v2 = ((const float4*)(z2 + (size_t)gw * DIM))[lane];
    float s1 = dot4(v1, v1), s2 = dot4(v2, v2), s12 = dot4(v1, v2);
#pragma unroll
    for (int o = 16; o; o >>= 1) {
        s1  += __shfl_xor_sync(0xffffffffu, s1, o);
        s2  += __shfl_xor_sync(0xffffffffu, s2, o);
        s12 += __shfl_xor_sync(0xffffffffu, s12, o);
    }
    float i1 = rsqrtf(s1), i2 = rsqrtf(s2);
    if (lane == 0) g_pos[gw] = s12 * i1 * i2;   // exact fp32 positive similarity
    g_f1[(size_t)gw * 32 + lane] = pack_fp8(v1, i1);
    g_f2[(size_t)gw * 32 + lane] = pack_fp8(v2, i2);
}

// ---------------- MMA for one nb-pair (fp8, 4 K-steps; R4-proven mapping) ----------------
__device__ __forceinline__ void mma_nbp_f8(
    uint32_t sB, const uint32_t a[4][4], int brow, int bsel, int nbp,
    float c[4][4])
{
    const int rx = brow & 7;
    const int nb0 = nbp * 2, nb1 = nb0 + 1;
    const uint32_t base0 = sB + (uint32_t)((nb0 * 16 + brow) * 128);
    const uint32_t base1 = sB + (uint32_t)((nb1 * 16 + brow) * 128);

    uint32_t b0[2][4], b1[2][4];
    ldsm4(b0[0], base0 + (uint32_t)((bsel ^ rx) << 4));
    ldsm4(b1[0], base1 + (uint32_t)((bsel ^ rx) << 4));

#pragma unroll
    for (int k = 0; k < 4; k++) {
        c[0][k] = 0.f; c[1][k] = 0.f; c[2][k] = 0.f; c[3][k] = 0.f;
    }
#pragma unroll
    for (int ks = 0; ks < 4; ks++) {
        const int cur = ks & 1, nxt = cur ^ 1;
        if (ks < 3) {
            const uint32_t co = (uint32_t)(((2 * (ks + 1) + bsel) ^ rx) << 4);
            ldsm4(b0[nxt], base0 + co);
            ldsm4(b1[nxt], base1 + co);
        }
        // n-lo block uses regs {0,2} (k-lo,k-hi); n-hi uses {1,3}
        mmafp8(c[0], a[ks], b0[cur][0], b0[cur][2]);
        mmafp8(c[1], a[ks], b0[cur][1], b0[cur][3]);
        mmafp8(c[2], a[ks], b1[cur][0], b1[cur][2]);
        mmafp8(c[3], a[ks], b1[cur][1], b1[cur][3]);
    }
}

// ---------------- epilogue pieces ----------------
// MODE: 0 row sums; 2 diag tile (mask j==i); 3 triangle tile (row + col sums)
template <int MODE>
__device__ __forceinline__ void epi_f(int nb, const float clo[4], const float chi[4],
                                      int r0, int c0, float& racc0, float& racc1,
                                      float cc[4][2], int ccb) {
    const int nbase = nb * 16;
#pragma unroll
    for (int i = 0; i < 4; i++) {
        const int jl = nbase + c0 + (i & 1);
        const int jh = jl + 8;
        const int rr = r0 + 8 * (i >> 1);
        float el = ex2f(fmaf(clo[i], K1F, -K1F));
        float eh = ex2f(fmaf(chi[i], K1F, -K1F));
        if (MODE == 2) {
            if (jl == rr) el = 0.f;
            if (jh == rr) eh = 0.f;
        }
        if (i >> 1) racc1 += el + eh; else racc0 += el + eh;
        if (MODE == 3) {
            cc[ccb][i & 1]     += el;
            cc[ccb + 1][i & 1] += eh;
        }
    }
}

template <int MODE>
__device__ __forceinline__ void epi_nbp(
    int nbp, const float c[4][4], int r0, int c0,
    float& racc0, float& racc1, uint32_t scAddr, int wid, int lane)
{
    const int nb0 = nbp * 2, nb1 = nb0 + 1;
    float cc[4][2];
    if (MODE == 3) {
#pragma unroll
        for (int k = 0; k < 4; k++) { cc[k][0] = 0.f; cc[k][1] = 0.f; }
    }
    epi_f<MODE>(nb0, c[0], c[1], r0, c0, racc0, racc1, cc, 0);
    epi_f<MODE>(nb1, c[2], c[3], r0, c0, racc0, racc1, cc, 2);

    if (MODE == 3) {
        // reduce over the 8 row-groups (lanes differing in bits 2..4)
#pragma unroll
        for (int k = 0; k < 4; k++) {
#pragma unroll
            for (int q = 0; q < 2; q++) {
                float vv = cc[k][q];
                vv += __shfl_xor_sync(0xffffffffu, vv, 4);
                vv += __shfl_xor_sync(0xffffffffu, vv, 8);
                vv += __shfl_xor_sync(0xffffffffu, vv, 16);
                cc[k][q] = vv;
            }
        }
        if (lane < 4) {
            uint32_t base = scAddr + (uint32_t)(wid * 512);
#pragma unroll
            for (int k = 0; k < 4; k++) {
                const int kk = nbp * 4 + k;
                uint32_t addr = base + (uint32_t)((kk * 4 + lane) * 8);
                asm volatile("st.shared.v2.f32 [%0], {%1, %2};"
                             :: "r"(addr), "f"(cc[k][0]), "f"(cc[k][1]) : "memory");
            }
        }
    }
}

// ---------------- tile consumer: epilogue pipelined one nbp behind ----------------
template <int MODE>
__device__ __forceinline__ void consume_tile_f8(
    uint32_t sB, const uint32_t a[4][4], int brow, int bsel,
    int r0, int c0, float& racc0, float& racc1,
    uint32_t scAddr, int wid, int lane)
{
    float cA[4][4], cB[4][4];
    mma_nbp_f8(sB, a, brow, bsel, 0, cA);
    mma_nbp_f8(sB, a, brow, bsel, 1, cB);
    epi_nbp<MODE>(0, cA, r0, c0, racc0, racc1, scAddr, wid, lane);
    mma_nbp_f8(sB, a, brow, bsel, 2, cA);
    epi_nbp<MODE>(1, cB, r0, c0, racc0, racc1, scAddr, wid, lane);
    mma_nbp_f8(sB, a, brow, bsel, 3, cB);
    epi_nbp<MODE>(2, cA, r0, c0, racc0, racc1, scAddr, wid, lane);
    epi_nbp<MODE>(3, cB, r0, c0, racc0, racc1, scAddr, wid, lane);
}

__device__ __forceinline__ int triT(int rt) { return rt * 128 - (rt * (rt - 1)) / 2; }

// ---------------- kernel 2: main fused loop (persistent, 296 CTAs, 2/SM) ----------------
__global__ void __launch_bounds__(256, 2) ncl_main_kernel() {
    extern __shared__ char smem[];
    const uint32_t sb = smem_u32(smem);
    const int tid = threadIdx.x;
    const int wid = tid >> 5;
    const int lane = tid & 31;
    const int bx = blockIdx.x;

    // copy slots: row = tid/2, 4 chunks of 16B starting at (tid&1)*4
    const int crow = tid >> 1;
    const int cc0 = (tid & 1) * 4;
    uint32_t dsto[4];
#pragma unroll
    for (int c = 0; c < 4; c++) dsto[c] = swz8(crow, cc0 + c);

    const int brow = lane & 15;          // ldsm row within 16-row block
    const int bsel = lane >> 4;          // k-chunk select
    const int arow = wid * 16 + (lane & 15);
    const int r0 = wid * 16 + (lane >> 2);
    const int c0 = (lane & 3) * 2;

#pragma unroll 1
    for (int phase = 0; phase < 2; phase++) {
        int u, u1;
        if (phase == 0) { u = (bx * UNITS_A) / NCTA;  u1 = ((bx + 1) * UNITS_A) / NCTA; }
        else            { u = (bx * UNITS_B) / NCTA;  u1 = ((bx + 1) * UNITS_B) / NCTA; }
        const char* bsrc = (const char*)(phase ? g_f1 : g_f2);

        while (u < u1) {
            int rt, bt;
            if (phase == 0) {
                rt = u >> 7;
                bt = u & 127;
            } else {
                float d = 128.5f * 128.5f - 2.0f * (float)u;
                rt = (int)(128.5f - sqrtf(d));
                if (rt < 0) rt = 0;
                if (rt > 127) rt = 127;
                while (rt < 127 && triT(rt + 1) <= u) rt++;
                while (rt > 0 && triT(rt) > u) rt--;
                bt = rt + (u - triT(rt));
            }
            const int cnt = min(u1 - u, 128 - bt);

            // one group: A tile + B tile 0
            {
                const char* srcA = (const char*)g_f1 + ((size_t)(rt * 128 + crow) * 128) + cc0 * 16;
                const char* srcB = bsrc + ((size_t)(bt * 128 + crow) * 128) + cc0 * 16;
#pragma unroll
                for (int c = 0; c < 4; c++) {
                    cp_async16(sb + SMEM_A + dsto[c], srcA + c * 16);
                    cp_async16(sb + SMEM_B(0) + dsto[c], srcB + c * 16);
                }
                cp_commit();
            }

            uint32_t a[4][4];
            float racc0 = 0.f, racc1 = 0.f;
            int pend_bt = -1, pend_slot = 0;

            for (int i = 0; i < cnt; i++) {
                const int btc = bt + i;
                cp_wait<0>();      // tile i (and A on i==0) resident
                __syncthreads();   // all copies visible; all warps done with tile i-1

                if (i == 0) {
#pragma unroll
                    for (int ks = 0; ks < 4; ks++)
                        ldsm4(a[ks], sb + SMEM_A + swz8(arow, 2 * ks + bsel));
                }
                // prefetch tile i+1 into the other stage
                if (i + 1 < cnt) {
                    const char* src = bsrc + ((size_t)((btc + 1) * 128 + crow) * 128) + cc0 * 16;
                    const uint32_t dst = sb + SMEM_B((i + 1) & 1);
#pragma unroll
                    for (int c = 0; c < 4; c++) cp_async16(dst + dsto[c], src + c * 16);
                    cp_commit();
                }
                // deferred gather of previous triangle tile's column sums
                if (pend_bt >= 0 && tid < 128) {
                    const float* sc = (const float*)(smem + SMEM_C + pend_slot * 4096);
                    float s = 0.f;
#pragma unroll
                    for (int w = 0; w < 8; w++) s += sc[w * 128 + tid];
                    atomicAdd(&g_rowsum[pend_bt * 128 + tid], s);
                }
                pend_bt = -1;

                const uint32_t sB = sb + SMEM_B(i & 1);
                if (phase == 0) {
                    consume_tile_f8<0>(sB, a, brow, bsel, r0, c0, racc0, racc1, 0, wid, lane);
                } else if (btc == rt) {
                    consume_tile_f8<2>(sB, a, brow, bsel, r0, c0, racc0, racc1, 0, wid, lane);
                } else {
                    const int slot = i & 1;
                    consume_tile_f8<3>(sB, a, brow, bsel, r0, c0, racc0, racc1,
                                       sb + SMEM_C + (uint32_t)(slot * 4096), wid, lane);
                    pend_bt = btc;
                    pend_slot = slot;
                }
            }

            __syncthreads();   // order last STS before drain
            if (pend_bt >= 0 && tid < 128) {
                const float* sc = (const float*)(smem + SMEM_C + pend_slot * 4096);
                float s = 0.f;
#pragma unroll
                for (int w = 0; w < 8; w++) s += sc[w * 128 + tid];
                atomicAdd(&g_rowsum[pend_bt * 128 + tid], s);
            }

            // row partial sums (quad holds disjoint col chunks of same rows)
            racc0 += __shfl_xor_sync(0xffffffffu, racc0, 1);
            racc0 += __shfl_xor_sync(0xffffffffu, racc0, 2);
            racc1 += __shfl_xor_sync(0xffffffffu, racc1, 1);
            racc1 += __shfl_xor_sync(0xffffffffu, racc1, 2);
            if ((lane & 3) == 0) {
                atomicAdd(&g_rowsum[rt * 128 + r0], racc0);
                atomicAdd(&g_rowsum[rt * 128 + r0 + 8], racc1);
            }
            u += cnt;
        }
    }
}

// ---------------- kernel 3: per-row loss + reductions ----------------
__global__ void __launch_bounds__(128) finalize1_kernel() {
    int i = blockIdx.x * 128 + threadIdx.x;
    int wid = threadIdx.x >> 5, lane = threadIdx.x & 31;
    float l = (1.0f - g_pos[i]) * INV_TAU + lg2f(g_rowsum[i]) * LN2F;
#pragma unroll
    for (int o = 16; o; o >>= 1) l += __shfl_xor_sync(0xffffffffu, l, o);
    __shared__ float red[4];
    if (lane == 0) red[wid] = l;
    __syncthreads();
    if (threadIdx.x == 0) g_bsum[blockIdx.x] = red[0] + red[1] + red[2] + red[3];
}

__global__ void finalize2_kernel(float* out) {
    int lane = threadIdx.x;
    float s = g_bsum[lane] + g_bsum[lane + 32] + g_bsum[lane + 64] + g_bsum[lane + 96];
#pragma unroll
    for (int o = 16; o; o >>= 1) s += __shfl_xor_sync(0xffffffffu, s, o);
    if (lane == 0) out[0] = s * (1.0f / (float)N_ROWS);
}

// ---------------- launch ----------------
extern "C" void kernel_launch(void* const* d_in, const int* in_sizes, int n_in,
                              void* d_out, int out_size) {
    const float* z1 = (const float*)d_in[0];
    const float* z2 = (const float*)d_in[1];
    float* out = (float*)d_out;
    (void)in_sizes; (void)n_in; (void)out_size;

    cudaFuncSetAttribute(ncl_main_kernel, cudaFuncAttributeMaxDynamicSharedMemorySize, SMEM_TOTAL);

    norm_kernel<<<N_ROWS / 8, 256>>>(z1, z2);
    ncl_main_kernel<<<NCTA, 256, SMEM_TOTAL>>>();
    finalize1_kernel<<<128, 128>>>();
    finalize2_kernel<<<1, 32>>>(out);
}

// round 13
// speedup vs baseline: 1.0221x; 1.0221x over previous
// NodeContrastiveLoss — fused fp8(e4m3) mma.sync + streaming LSE, z1z1 triangle.
// R13: rate-fork test: e4m3 QMMA with **f16 accumulator** (Ada precedent: 2x
// the f32-acc rate). R12 proved tensor-saturation at f32-acc rt~24; if f16-acc
// is rt~12 the wall halves. Structure = R11 (R12's epi pipelining was neutral);
// keeps 2 CTAs/SM, balanced phases, deferred col-flush, exact fp32 pos.
#include <cuda_runtime.h>
#include <cuda_fp8.h>
#include <cuda_fp16.h>
#include <cstdint>
#include <cstddef>
#include <cmath>

#define N_ROWS 16384
#define DIM    128
#define NCTA   296
#define UNITS_A 16384        // z1*z2^T: 128 rt x 128 bt
#define UNITS_B 8256         // triangular z1*z1^T units (incl. diagonal)

#define INV_TAU 14.285714285714286f
#define K1F     20.609929155556620f    // log2(e)/tau
#define LN2F    0.6931471805599453f

static __device__ uint32_t g_f1[(size_t)N_ROWS * 32];   // e4m3 rows, 4 packed/word
static __device__ uint32_t g_f2[(size_t)N_ROWS * 32];
static __device__ float    g_pos[N_ROWS];
static __device__ float    g_rowsum[N_ROWS];
static __device__ float    g_bsum[128];

// ---------------- helpers ----------------
__device__ __forceinline__ uint32_t smem_u32(const void* p) {
    uint32_t r;
    asm("{ .reg .u64 t; cvta.to.shared.u64 t, %1; cvt.u32.u64 %0, t; }" : "=r"(r) : "l"(p));
    return r;
}
__device__ __forceinline__ void cp_async16(uint32_t dst, const void* src) {
    asm volatile("cp.async.cg.shared.global [%0], [%1], 16;" :: "r"(dst), "l"(src) : "memory");
}
__device__ __forceinline__ void cp_commit() { asm volatile("cp.async.commit_group;" ::: "memory"); }
template <int N>
__device__ __forceinline__ void cp_wait() { asm volatile("cp.async.wait_group %0;" :: "n"(N) : "memory"); }

__device__ __forceinline__ void ldsm4(uint32_t r[4], uint32_t addr) {
    asm volatile("ldmatrix.sync.aligned.m8n8.x4.shared.b16 {%0,%1,%2,%3}, [%4];"
                 : "=r"(r[0]), "=r"(r[1]), "=r"(r[2]), "=r"(r[3]) : "r"(addr));
}
// fp8 e4m3 mma with f16 accumulator: D,C = 2 b32 regs (4 packed halves)
__device__ __forceinline__ void mmafp8h(uint32_t c[2], const uint32_t a[4], uint32_t b0, uint32_t b1) {
    asm volatile(
        "mma.sync.aligned.m16n8k32.row.col.f16.e4m3.e4m3.f16 "
        "{%0,%1}, {%2,%3,%4,%5}, {%6,%7}, {%0,%1};"
        : "+r"(c[0]), "+r"(c[1])
        : "r"(a[0]), "r"(a[1]), "r"(a[2]), "r"(a[3]), "r"(b0), "r"(b1));
}
__device__ __forceinline__ float ex2f(float x) { float y; asm("ex2.approx.f32 %0, %1;" : "=f"(y) : "f"(x)); return y; }
__device__ __forceinline__ float lg2f(float x) { float y; asm("lg2.approx.f32 %0, %1;" : "=f"(y) : "f"(x)); return y; }

// fp8 tile: 128 rows x 128 B (8 chunks of 16 B), 3-bit XOR swizzle (R4-proven).
__device__ __forceinline__ uint32_t swz8(int row, int c) {
    return (uint32_t)(row * 128 + (((c ^ row) & 7) << 4));
}

// ---------------- SMEM layout (dynamic, 56 KB/CTA) ----------------
#define SMEM_A  0
#define SMEM_B(s) (16384 + (s) * 16384)   // 2 stages x 16 KB
#define SMEM_C  49152                     // 2 x 4 KB col-sum staging slots
#define SMEM_TOTAL 57344

// ---------------- kernel 1: normalize + e4m3 + exact pos ----------------
__device__ __forceinline__ float dot4(float4 a, float4 b) {
    return a.x * b.x + a.y * b.y + a.z * b.z + a.w * b.w;
}
__device__ __forceinline__ uint32_t pack_fp8(float4 v, float s) {
    __nv_fp8x2_storage_t lo = __nv_cvt_float2_to_fp8x2(make_float2(v.x * s, v.y * s),
                                                       __NV_SATFINITE, __NV_E4M3);
    __nv_fp8x2_storage_t hi = __nv_cvt_float2_to_fp8x2(make_float2(v.z * s, v.w * s),
                                                       __NV_SATFINITE, __NV_E4M3);
    return (uint32_t)lo | ((uint32_t)hi << 16);
}
__global__ void __launch_bounds__(256) norm_kernel(const float* __restrict__ z1,
                                                   const float* __restrict__ z2) {
    int gw = blockIdx.x * 8 + (threadIdx.x >> 5);
    int lane = threadIdx.x & 31;
    if (threadIdx.x < 8) g_rowsum[blockIdx.x * 8 + threadIdx.x] = 0.f;
    float4 v1 = ((const float4*)(z1 + (size_t)gw * DIM))[lane];
    float4 v2 = ((const float4*)(z2 + (size_t)gw * DIM))[lane];
    float s1 = dot4(v1, v1), s2 = dot4(v2, v2), s12 = dot4(v1, v2);
#pragma unroll
    for (int o = 16; o; o >>= 1) {
        s1  += __shfl_xor_sync(0xffffffffu, s1, o);
        s2  += __shfl_xor_sync(0xffffffffu, s2, o);
        s12 += __shfl_xor_sync(0xffffffffu, s12, o);
    }
    float i1 = rsqrtf(s1), i2 = rsqrtf(s2);
    if (lane == 0) g_pos[gw] = s12 * i1 * i2;   // exact fp32 positive similarity
    g_f1[(size_t)gw * 32 + lane] = pack_fp8(v1, i1);
    g_f2[(size_t)gw * 32 + lane] = pack_fp8(v2, i2);
}

// ---------------- epilogue for one 8-col block (f16-acc pair) ----------------
// ch[0]: row r0 cols j0,j1 ; ch[1]: row r0+8 cols j0,j1
// MODE: 0 row sums; 2 diag tile (mask j==i); 3 triangle tile (row + col sums)
template <int MODE>
__device__ __forceinline__ void epi_h8(int colb, const uint32_t ch[2],
                                       int r0, int c0, float& racc0, float& racc1,
                                       float cc[4][2], int ccIdx) {
    const int j0 = colb + c0, j1 = j0 + 1;
    float2 lo = __half22float2(*(const __half2*)&ch[0]);
    float2 hi = __half22float2(*(const __half2*)&ch[1]);
    float e00 = ex2f(fmaf(lo.x, K1F, -K1F));
    float e01 = ex2f(fmaf(lo.y, K1F, -K1F));
    float e10 = ex2f(fmaf(hi.x, K1F, -K1F));
    float e11 = ex2f(fmaf(hi.y, K1F, -K1F));
    if (MODE == 2) {
        if (j0 == r0)     e00 = 0.f;
        if (j1 == r0)     e01 = 0.f;
        if (j0 == r0 + 8) e10 = 0.f;
        if (j1 == r0 + 8) e11 = 0.f;
    }
    racc0 += e00 + e01;
    racc1 += e10 + e11;
    if (MODE == 3) {
        cc[ccIdx][0] += e00 + e10;
        cc[ccIdx][1] += e01 + e11;
    }
}

// ---------------- tile consumer (fp8/f16acc, 4 K-steps; R4-proven mapping) ----------------
template <int MODE>
__device__ __forceinline__ void consume_tile_f8(
    uint32_t sB, const uint32_t a[4][4], int brow, int bsel,
    int r0, int c0, float& racc0, float& racc1,
    uint32_t scAddr, int wid, int lane)
{
    const int rx = brow & 7;
#pragma unroll
    for (int nbp = 0; nbp < 4; nbp++) {
        const int nb0 = nbp * 2, nb1 = nb0 + 1;
        const uint32_t base0 = sB + (uint32_t)((nb0 * 16 + brow) * 128);
        const uint32_t base1 = sB + (uint32_t)((nb1 * 16 + brow) * 128);

        uint32_t b0[2][4], b1[2][4];
        ldsm4(b0[0], base0 + (uint32_t)((bsel ^ rx) << 4));
        ldsm4(b1[0], base1 + (uint32_t)((bsel ^ rx) << 4));

        uint32_t c00[2] = {0u, 0u}, c01[2] = {0u, 0u};
        uint32_t c10[2] = {0u, 0u}, c11[2] = {0u, 0u};

#pragma unroll
        for (int ks = 0; ks < 4; ks++) {
            const int cur = ks & 1, nxt = cur ^ 1;
            if (ks < 3) {
                const uint32_t co = (uint32_t)(((2 * (ks + 1) + bsel) ^ rx) << 4);
                ldsm4(b0[nxt], base0 + co);
                ldsm4(b1[nxt], base1 + co);
            }
            // n-lo block uses regs {0,2} (k-lo,k-hi); n-hi uses {1,3}
            mmafp8h(c00, a[ks], b0[cur][0], b0[cur][2]);
            mmafp8h(c01, a[ks], b0[cur][1], b0[cur][3]);
            mmafp8h(c10, a[ks], b1[cur][0], b1[cur][2]);
            mmafp8h(c11, a[ks], b1[cur][1], b1[cur][3]);
        }

        float cc[4][2];
        if (MODE == 3) {
#pragma unroll
            for (int k = 0; k < 4; k++) { cc[k][0] = 0.f; cc[k][1] = 0.f; }
        }
        epi_h8<MODE>(nbp * 32,      c00, r0, c0, racc0, racc1, cc, 0);
        epi_h8<MODE>(nbp * 32 + 8,  c01, r0, c0, racc0, racc1, cc, 1);
        epi_h8<MODE>(nbp * 32 + 16, c10, r0, c0, racc0, racc1, cc, 2);
        epi_h8<MODE>(nbp * 32 + 24, c11, r0, c0, racc0, racc1, cc, 3);

        if (MODE == 3) {
            // reduce over the 8 row-groups (lanes differing in bits 2..4)
#pragma unroll
            for (int k = 0; k < 4; k++) {
#pragma unroll
                for (int q = 0; q < 2; q++) {
                    float vv = cc[k][q];
                    vv += __shfl_xor_sync(0xffffffffu, vv, 4);
                    vv += __shfl_xor_sync(0xffffffffu, vv, 8);
                    vv += __shfl_xor_sync(0xffffffffu, vv, 16);
                    cc[k][q] = vv;
                }
            }
            if (lane < 4) {
                uint32_t base = scAddr + (uint32_t)(wid * 512);
#pragma unroll
                for (int k = 0; k < 4; k++) {
                    const int kk = nbp * 4 + k;
                    uint32_t addr = base + (uint32_t)((kk * 4 + lane) * 8);
                    asm volatile("st.shared.v2.f32 [%0], {%1, %2};"
                                 :: "r"(addr), "f"(cc[k][0]), "f"(cc[k][1]) : "memory");
                }
            }
        }
    }
}

__device__ __forceinline__ int triT(int rt) { return rt * 128 - (rt * (rt - 1)) / 2; }

// ---------------- kernel 2: main fused loop (persistent, 296 CTAs, 2/SM) ----------------
__global__ void __launch_bounds__(256, 2) ncl_main_kernel() {
    extern __shared__ char smem[];
    const uint32_t sb = smem_u32(smem);
    const int tid = threadIdx.x;
    const int wid = tid >> 5;
    const int lane = tid & 31;
    const int bx = blockIdx.x;

    // copy slots: row = tid/2, 4 chunks of 16B starting at (tid&1)*4
    const int crow = tid >> 1;
    const int cc0 = (tid & 1) * 4;
    uint32_t dsto[4];
#pragma unroll
    for (int c = 0; c < 4; c++) dsto[c] = swz8(crow, cc0 + c);

    const int brow = lane & 15;          // ldsm row within 16-row block
    const int bsel = lane >> 4;          // k-chunk select
    const int arow = wid * 16 + (lane & 15);
    const int r0 = wid * 16 + (lane >> 2);
    const int c0 = (lane & 3) * 2;

#pragma unroll 1
    for (int phase = 0; phase < 2; phase++) {
        int u, u1;
        if (phase == 0) { u = (bx * UNITS_A) / NCTA;  u1 = ((bx + 1) * UNITS_A) / NCTA; }
        else            { u = (bx * UNITS_B) / NCTA;  u1 = ((bx + 1) * UNITS_B) / NCTA; }
        const char* bsrc = (const char*)(phase ? g_f1 : g_f2);

        while (u < u1) {
            int rt, bt;
            if (phase == 0) {
                rt = u >> 7;
                bt = u & 127;
            } else {
                float d = 128.5f * 128.5f - 2.0f * (float)u;
                rt = (int)(128.5f - sqrtf(d));
                if (rt < 0) rt = 0;
                if (rt > 127) rt = 127;
                while (rt < 127 && triT(rt + 1) <= u) rt++;
                while (rt > 0 && triT(rt) > u) rt--;
                bt = rt + (u - triT(rt));
            }
            const int cnt = min(u1 - u, 128 - bt);

            // one group: A tile + B tile 0
            {
                const char* srcA = (const char*)g_f1 + ((size_t)(rt * 128 + crow) * 128) + cc0 * 16;
                const char* srcB = bsrc + ((size_t)(bt * 128 + crow) * 128) + cc0 * 16;
#pragma unroll
                for (int c = 0; c < 4; c++) {
                    cp_async16(sb + SMEM_A + dsto[c], srcA + c * 16);
                    cp_async16(sb + SMEM_B(0) + dsto[c], srcB + c * 16);
                }
                cp_commit();
            }

            uint32_t a[4][4];
            float racc0 = 0.f, racc1 = 0.f;
            int pend_bt = -1, pend_slot = 0;

            for (int i = 0; i < cnt; i++) {
                const int btc = bt + i;
                cp_wait<0>();      // tile i (and A on i==0) resident
                __syncthreads();   // all copies visible; all warps done with tile i-1

                if (i == 0) {
#pragma unroll
                    for (int ks = 0; ks < 4; ks++)
                        ldsm4(a[ks], sb + SMEM_A + swz8(arow, 2 * ks + bsel));
                }
                // prefetch tile i+1 into the other stage
                if (i + 1 < cnt) {
                    const char* src = bsrc + ((size_t)((btc + 1) * 128 + crow) * 128) + cc0 * 16;
                    const uint32_t dst = sb + SMEM_B((i + 1) & 1);
#pragma unroll
                    for (int c = 0; c < 4; c++) cp_async16(dst + dsto[c], src + c * 16);
                    cp_commit();
                }
                // deferred gather of previous triangle tile's column sums
                if (pend_bt >= 0 && tid < 128) {
                    const float* sc = (const float*)(smem + SMEM_C + pend_slot * 4096);
                    float s = 0.f;
#pragma unroll
                    for (int w = 0; w < 8; w++) s += sc[w * 128 + tid];
                    atomicAdd(&g_rowsum[pend_bt * 128 + tid], s);
                }
                pend_bt = -1;

                const uint32_t sB = sb + SMEM_B(i & 1);
                if (phase == 0) {
                    consume_tile_f8<0>(sB, a, brow, bsel, r0, c0, racc0, racc1, 0, wid, lane);
                } else if (btc == rt) {
                    consume_tile_f8<2>(sB, a, brow, bsel, r0, c0, racc0, racc1, 0, wid, lane);
                } else {
                    const int slot = i & 1;
                    consume_tile_f8<3>(sB, a, brow, bsel, r0, c0, racc0, racc1,
                                       sb + SMEM_C + (uint32_t)(slot * 4096), wid, lane);
                    pend_bt = btc;
                    pend_slot = slot;
                }
            }

            __syncthreads();   // order last STS before drain
            if (pend_bt >= 0 && tid < 128) {
                const float* sc = (const float*)(smem + SMEM_C + pend_slot * 4096);
                float s = 0.f;
#pragma unroll
                for (int w = 0; w < 8; w++) s += sc[w * 128 + tid];
                atomicAdd(&g_rowsum[pend_bt * 128 + tid], s);
            }

            // row partial sums (quad holds disjoint col chunks of same rows)
            racc0 += __shfl_xor_sync(0xffffffffu, racc0, 1);
            racc0 += __shfl_xor_sync(0xffffffffu, racc0, 2);
            racc1 += __shfl_xor_sync(0xffffffffu, racc1, 1);
            racc1 += __shfl_xor_sync(0xffffffffu, racc1, 2);
            if ((lane & 3) == 0) {
                atomicAdd(&g_rowsum[rt * 128 + r0], racc0);
                atomicAdd(&g_rowsum[rt * 128 + r0 + 8], racc1);
            }
            u += cnt;
        }
    }
}

// ---------------- kernel 3: per-row loss + reductions ----------------
__global__ void __launch_bounds__(128) finalize1_kernel() {
    int i = blockIdx.x * 128 + threadIdx.x;
    int wid = threadIdx.x >> 5, lane = threadIdx.x & 31;
    float l = (1.0f - g_pos[i]) * INV_TAU + lg2f(g_rowsum[i]) * LN2F;
#pragma unroll
    for (int o = 16; o; o >>= 1) l += __shfl_xor_sync(0xffffffffu, l, o);
    __shared__ float red[4];
    if (lane == 0) red[wid] = l;
    __syncthreads();
    if (threadIdx.x == 0) g_bsum[blockIdx.x] = red[0] + red[1] + red[2] + red[3];
}

__global__ void finalize2_kernel(float* out) {
    int lane = threadIdx.x;
    float s = g_bsum[lane] + g_bsum[lane + 32] + g_bsum[lane + 64] + g_bsum[lane + 96];
#pragma unroll
    for (int o = 16; o; o >>= 1) s += __shfl_xor_sync(0xffffffffu, s, o);
    if (lane == 0) out[0] = s * (1.0f / (float)N_ROWS);
}

// ---------------- launch ----------------
extern "C" void kernel_launch(void* const* d_in, const int* in_sizes, int n_in,
                              void* d_out, int out_size) {
    const float* z1 = (const float*)d_in[0];
    const float* z2 = (const float*)d_in[1];
    float* out = (float*)d_out;
    (void)in_sizes; (void)n_in; (void)out_size;

    cudaFuncSetAttribute(ncl_main_kernel, cudaFuncAttributeMaxDynamicSharedMemorySize, SMEM_TOTAL);

    norm_kernel<<<N_ROWS / 8, 256>>>(z1, z2);
    ncl_main_kernel<<<NCTA, 256, SMEM_TOTAL>>>();
    finalize1_kernel<<<128, 128>>>();
    finalize2_kernel<<<1, 32>>>(out);
}

// round 14
// speedup vs baseline: 1.0268x; 1.0046x over previous
// NodeContrastiveLoss — fused fp8(e4m3) mma.sync + streaming LSE, z1z1 triangle.
// R13: rate-fork test: e4m3 QMMA with **f16 accumulator** (Ada precedent: 2x
// the f32-acc rate). R12 proved tensor-saturation at f32-acc rt~24; if f16-acc
// is rt~12 the wall halves. Structure = R11 (R12's epi pipelining was neutral);
// keeps 2 CTAs/SM, balanced phases, deferred col-flush, exact fp32 pos.
#include <cuda_runtime.h>
#include <cuda_fp8.h>
#include <cuda_fp16.h>
#include <cstdint>
#include <cstddef>
#include <cmath>

#define N_ROWS 16384
#define DIM    128
#define NCTA   296
#define UNITS_A 16384        // z1*z2^T: 128 rt x 128 bt
#define UNITS_B 8256         // triangular z1*z1^T units (incl. diagonal)

#define INV_TAU 14.285714285714286f
#define K1F     20.609929155556620f    // log2(e)/tau
#define LN2F    0.6931471805599453f

static __device__ uint32_t g_f1[(size_t)N_ROWS * 32];   // e4m3 rows, 4 packed/word
static __device__ uint32_t g_f2[(size_t)N_ROWS * 32];
static __device__ float    g_pos[N_ROWS];
static __device__ float    g_rowsum[N_ROWS];
static __device__ float    g_bsum[128];

// ---------------- helpers ----------------
__device__ __forceinline__ uint32_t smem_u32(const void* p) {
    uint32_t r;
    asm("{ .reg .u64 t; cvta.to.shared.u64 t, %1; cvt.u32.u64 %0, t; }" : "=r"(r) : "l"(p));
    return r;
}
__device__ __forceinline__ void cp_async16(uint32_t dst, const void* src) {
    asm volatile("cp.async.cg.shared.global [%0], [%1], 16;" :: "r"(dst), "l"(src) : "memory");
}
__device__ __forceinline__ void cp_commit() { asm volatile("cp.async.commit_group;" ::: "memory"); }
template <int N>
__device__ __forceinline__ void cp_wait() { asm volatile("cp.async.wait_group %0;" :: "n"(N) : "memory"); }

__device__ __forceinline__ void ldsm4(uint32_t r[4], uint32_t addr) {
    asm volatile("ldmatrix.sync.aligned.m8n8.x4.shared.b16 {%0,%1,%2,%3}, [%4];"
                 : "=r"(r[0]), "=r"(r[1]), "=r"(r[2]), "=r"(r[3]) : "r"(addr));
}
// fp8 e4m3 mma with f16 accumulator: D,C = 2 b32 regs (4 packed halves)
__device__ __forceinline__ void mmafp8h(uint32_t c[2], const uint32_t a[4], uint32_t b0, uint32_t b1) {
    asm volatile(
        "mma.sync.aligned.m16n8k32.row.col.f16.e4m3.e4m3.f16 "
        "{%0,%1}, {%2,%3,%4,%5}, {%6,%7}, {%0,%1};"
        : "+r"(c[0]), "+r"(c[1])
        : "r"(a[0]), "r"(a[1]), "r"(a[2]), "r"(a[3]), "r"(b0), "r"(b1));
}
__device__ __forceinline__ float ex2f(float x) { float y; asm("ex2.approx.f32 %0, %1;" : "=f"(y) : "f"(x)); return y; }
__device__ __forceinline__ float lg2f(float x) { float y; asm("lg2.approx.f32 %0, %1;" : "=f"(y) : "f"(x)); return y; }

// fp8 tile: 128 rows x 128 B (8 chunks of 16 B), 3-bit XOR swizzle (R4-proven).
__device__ __forceinline__ uint32_t swz8(int row, int c) {
    return (uint32_t)(row * 128 + (((c ^ row) & 7) << 4));
}

// ---------------- SMEM layout (dynamic, 56 KB/CTA) ----------------
#define SMEM_A  0
#define SMEM_B(s) (16384 + (s) * 16384)   // 2 stages x 16 KB
#define SMEM_C  49152                     // 2 x 4 KB col-sum staging slots
#define SMEM_TOTAL 57344

// ---------------- kernel 1: normalize + e4m3 + exact pos ----------------
__device__ __forceinline__ float dot4(float4 a, float4 b) {
    return a.x * b.x + a.y * b.y + a.z * b.z + a.w * b.w;
}
__device__ __forceinline__ uint32_t pack_fp8(float4 v, float s) {
    __nv_fp8x2_storage_t lo = __nv_cvt_float2_to_fp8x2(make_float2(v.x * s, v.y * s),
                                                       __NV_SATFINITE, __NV_E4M3);
    __nv_fp8x2_storage_t hi = __nv_cvt_float2_to_fp8x2(make_float2(v.z * s, v.w * s),
                                                       __NV_SATFINITE, __NV_E4M3);
    return (uint32_t)lo | ((uint32_t)hi << 16);
}
__global__ void __launch_bounds__(256) norm_kernel(const float* __restrict__ z1,
                                                   const float* __restrict__ z2) {
    int gw = blockIdx.x * 8 + (threadIdx.x >> 5);
    int lane = threadIdx.x & 31;
    if (threadIdx.x < 8) g_rowsum[blockIdx.x * 8 + threadIdx.x] = 0.f;
    float4 v1 = ((const float4*)(z1 + (size_t)gw * DIM))[lane];
    float4 v2 = ((const float4*)(z2 + (size_t)gw * DIM))[lane];
    float s1 = dot4(v1, v1), s2 = dot4(v2, v2), s12 = dot4(v1, v2);
#pragma unroll
    for (int o = 16; o; o >>= 1) {
        s1  += __shfl_xor_sync(0xffffffffu, s1, o);
        s2  += __shfl_xor_sync(0xffffffffu, s2, o);
        s12 += __shfl_xor_sync(0xffffffffu, s12, o);
    }
    float i1 = rsqrtf(s1), i2 = rsqrtf(s2);
    if (lane == 0) g_pos[gw] = s12 * i1 * i2;   // exact fp32 positive similarity
    g_f1[(size_t)gw * 32 + lane] = pack_fp8(v1, i1);
    g_f2[(size_t)gw * 32 + lane] = pack_fp8(v2, i2);
}

// ---------------- epilogue for one 8-col block (f16-acc pair) ----------------
// ch[0]: row r0 cols j0,j1 ; ch[1]: row r0+8 cols j0,j1
// MODE: 0 row sums; 2 diag tile (mask j==i); 3 triangle tile (row + col sums)
template <int MODE>
__device__ __forceinline__ void epi_h8(int colb, const uint32_t ch[2],
                                       int r0, int c0, float& racc0, float& racc1,
                                       float cc[4][2], int ccIdx) {
    const int j0 = colb + c0, j1 = j0 + 1;
    float2 lo = __half22float2(*(const __half2*)&ch[0]);
    float2 hi = __half22float2(*(const __half2*)&ch[1]);
    float e00 = ex2f(fmaf(lo.x, K1F, -K1F));
    float e01 = ex2f(fmaf(lo.y, K1F, -K1F));
    float e10 = ex2f(fmaf(hi.x, K1F, -K1F));
    float e11 = ex2f(fmaf(hi.y, K1F, -K1F));
    if (MODE == 2) {
        if (j0 == r0)     e00 = 0.f;
        if (j1 == r0)     e01 = 0.f;
        if (j0 == r0 + 8) e10 = 0.f;
        if (j1 == r0 + 8) e11 = 0.f;
    }
    racc0 += e00 + e01;
    racc1 += e10 + e11;
    if (MODE == 3) {
        cc[ccIdx][0] += e00 + e10;
        cc[ccIdx][1] += e01 + e11;
    }
}

// ---------------- tile consumer (fp8/f16acc, 4 K-steps; R4-proven mapping) ----------------
template <int MODE>
__device__ __forceinline__ void consume_tile_f8(
    uint32_t sB, const uint32_t a[4][4], int brow, int bsel,
    int r0, int c0, float& racc0, float& racc1,
    uint32_t scAddr, int wid, int lane)
{
    const int rx = brow & 7;
#pragma unroll
    for (int nbp = 0; nbp < 4; nbp++) {
        const int nb0 = nbp * 2, nb1 = nb0 + 1;
        const uint32_t base0 = sB + (uint32_t)((nb0 * 16 + brow) * 128);
        const uint32_t base1 = sB + (uint32_t)((nb1 * 16 + brow) * 128);

        uint32_t b0[2][4], b1[2][4];
        ldsm4(b0[0], base0 + (uint32_t)((bsel ^ rx) << 4));
        ldsm4(b1[0], base1 + (uint32_t)((bsel ^ rx) << 4));

        uint32_t c00[2] = {0u, 0u}, c01[2] = {0u, 0u};
        uint32_t c10[2] = {0u, 0u}, c11[2] = {0u, 0u};

#pragma unroll
        for (int ks = 0; ks < 4; ks++) {
            const int cur = ks & 1, nxt = cur ^ 1;
            if (ks < 3) {
                const uint32_t co = (uint32_t)(((2 * (ks + 1) + bsel) ^ rx) << 4);
                ldsm4(b0[nxt], base0 + co);
                ldsm4(b1[nxt], base1 + co);
            }
            // n-lo block uses regs {0,2} (k-lo,k-hi); n-hi uses {1,3}
            mmafp8h(c00, a[ks], b0[cur][0], b0[cur][2]);
            mmafp8h(c01, a[ks], b0[cur][1], b0[cur][3]);
            mmafp8h(c10, a[ks], b1[cur][0], b1[cur][2]);
            mmafp8h(c11, a[ks], b1[cur][1], b1[cur][3]);
        }

        float cc[4][2];
        if (MODE == 3) {
#pragma unroll
            for (int k = 0; k < 4; k++) { cc[k][0] = 0.f; cc[k][1] = 0.f; }
        }
        epi_h8<MODE>(nbp * 32,      c00, r0, c0, racc0, racc1, cc, 0);
        epi_h8<MODE>(nbp * 32 + 8,  c01, r0, c0, racc0, racc1, cc, 1);
        epi_h8<MODE>(nbp * 32 + 16, c10, r0, c0, racc0, racc1, cc, 2);
        epi_h8<MODE>(nbp * 32 + 24, c11, r0, c0, racc0, racc1, cc, 3);

        if (MODE == 3) {
            // reduce over the 8 row-groups (lanes differing in bits 2..4)
#pragma unroll
            for (int k = 0; k < 4; k++) {
#pragma unroll
                for (int q = 0; q < 2; q++) {
                    float vv = cc[k][q];
                    vv += __shfl_xor_sync(0xffffffffu, vv, 4);
                    vv += __shfl_xor_sync(0xffffffffu, vv, 8);
                    vv += __shfl_xor_sync(0xffffffffu, vv, 16);
                    cc[k][q] = vv;
                }
            }
            if (lane < 4) {
                uint32_t base = scAddr + (uint32_t)(wid * 512);
#pragma unroll
                for (int k = 0; k < 4; k++) {
                    const int kk = nbp * 4 + k;
                    uint32_t addr = base + (uint32_t)((kk * 4 + lane) * 8);
                    asm volatile("st.shared.v2.f32 [%0], {%1, %2};"
                                 :: "r"(addr), "f"(cc[k][0]), "f"(cc[k][1]) : "memory");
                }
            }
        }
    }
}

__device__ __forceinline__ int triT(int rt) { return rt * 128 - (rt * (rt - 1)) / 2; }

// ---------------- kernel 2: main fused loop (persistent, 296 CTAs, 2/SM) ----------------
__global__ void __launch_bounds__(256, 2) ncl_main_kernel() {
    extern __shared__ char smem[];
    const uint32_t sb = smem_u32(smem);
    const int tid = threadIdx.x;
    const int wid = tid >> 5;
    const int lane = tid & 31;
    const int bx = blockIdx.x;

    // copy slots: row = tid/2, 4 chunks of 16B starting at (tid&1)*4
    const int crow = tid >> 1;
    const int cc0 = (tid & 1) * 4;
    uint32_t dsto[4];
#pragma unroll
    for (int c = 0; c < 4; c++) dsto[c] = swz8(crow, cc0 + c);

    const int brow = lane & 15;          // ldsm row within 16-row block
    const int bsel = lane >> 4;          // k-chunk select
    const int arow = wid * 16 + (lane & 15);
    const int r0 = wid * 16 + (lane >> 2);
    const int c0 = (lane & 3) * 2;

#pragma unroll 1
    for (int phase = 0; phase < 2; phase++) {
        int u, u1;
        if (phase == 0) { u = (bx * UNITS_A) / NCTA;  u1 = ((bx + 1) * UNITS_A) / NCTA; }
        else            { u = (bx * UNITS_B) / NCTA;  u1 = ((bx + 1) * UNITS_B) / NCTA; }
        const char* bsrc = (const char*)(phase ? g_f1 : g_f2);

        while (u < u1) {
            int rt, bt;
            if (phase == 0) {
                rt = u >> 7;
                bt = u & 127;
            } else {
                float d = 128.5f * 128.5f - 2.0f * (float)u;
                rt = (int)(128.5f - sqrtf(d));
                if (rt < 0) rt = 0;
                if (rt > 127) rt = 127;
                while (rt < 127 && triT(rt + 1) <= u) rt++;
                while (rt > 0 && triT(rt) > u) rt--;
                bt = rt + (u - triT(rt));
            }
            const int cnt = min(u1 - u, 128 - bt);

            // one group: A tile + B tile 0
            {
                const char* srcA = (const char*)g_f1 + ((size_t)(rt * 128 + crow) * 128) + cc0 * 16;
                const char* srcB = bsrc + ((size_t)(bt * 128 + crow) * 128) + cc0 * 16;
#pragma unroll
                for (int c = 0; c < 4; c++) {
                    cp_async16(sb + SMEM_A + dsto[c], srcA + c * 16);
                    cp_async16(sb + SMEM_B(0) + dsto[c], srcB + c * 16);
                }
                cp_commit();
            }

            uint32_t a[4][4];
            float racc0 = 0.f, racc1 = 0.f;
            int pend_bt = -1, pend_slot = 0;

            for (int i = 0; i < cnt; i++) {
                const int btc = bt + i;
                cp_wait<0>();      // tile i (and A on i==0) resident
                __syncthreads();   // all copies visible; all warps done with tile i-1

                if (i == 0) {
#pragma unroll
                    for (int ks = 0; ks < 4; ks++)
                        ldsm4(a[ks], sb + SMEM_A + swz8(arow, 2 * ks + bsel));
                }
                // prefetch tile i+1 into the other stage
                if (i + 1 < cnt) {
                    const char* src = bsrc + ((size_t)((btc + 1) * 128 + crow) * 128) + cc0 * 16;
                    const uint32_t dst = sb + SMEM_B((i + 1) & 1);
#pragma unroll
                    for (int c = 0; c < 4; c++) cp_async16(dst + dsto[c], src + c * 16);
                    cp_commit();
                }
                // deferred gather of previous triangle tile's column sums
                if (pend_bt >= 0 && tid < 128) {
                    const float* sc = (const float*)(smem + SMEM_C + pend_slot * 4096);
                    float s = 0.f;
#pragma unroll
                    for (int w = 0; w < 8; w++) s += sc[w * 128 + tid];
                    atomicAdd(&g_rowsum[pend_bt * 128 + tid], s);
                }
                pend_bt = -1;

                const uint32_t sB = sb + SMEM_B(i & 1);
                if (phase == 0) {
                    consume_tile_f8<0>(sB, a, brow, bsel, r0, c0, racc0, racc1, 0, wid, lane);
                } else if (btc == rt) {
                    consume_tile_f8<2>(sB, a, brow, bsel, r0, c0, racc0, racc1, 0, wid, lane);
                } else {
                    const int slot = i & 1;
                    consume_tile_f8<3>(sB, a, brow, bsel, r0, c0, racc0, racc1,
                                       sb + SMEM_C + (uint32_t)(slot * 4096), wid, lane);
                    pend_bt = btc;
                    pend_slot = slot;
                }
            }

            __syncthreads();   // order last STS before drain
            if (pend_bt >= 0 && tid < 128) {
                const float* sc = (const float*)(smem + SMEM_C + pend_slot * 4096);
                float s = 0.f;
#pragma unroll
                for (int w = 0; w < 8; w++) s += sc[w * 128 + tid];
                atomicAdd(&g_rowsum[pend_bt * 128 + tid], s);
            }

            // row partial sums (quad holds disjoint col chunks of same rows)
            racc0 += __shfl_xor_sync(0xffffffffu, racc0, 1);
            racc0 += __shfl_xor_sync(0xffffffffu, racc0, 2);
            racc1 += __shfl_xor_sync(0xffffffffu, racc1, 1);
            racc1 += __shfl_xor_sync(0xffffffffu, racc1, 2);
            if ((lane & 3) == 0) {
                atomicAdd(&g_rowsum[rt * 128 + r0], racc0);
                atomicAdd(&g_rowsum[rt * 128 + r0 + 8], racc1);
            }
            u += cnt;
        }
    }
}

// ---------------- kernel 3: per-row loss + reductions ----------------
__global__ void __launch_bounds__(128) finalize1_kernel() {
    int i = blockIdx.x * 128 + threadIdx.x;
    int wid = threadIdx.x >> 5, lane = threadIdx.x & 31;
    float l = (1.0f - g_pos[i]) * INV_TAU + lg2f(g_rowsum[i]) * LN2F;
#pragma unroll
    for (int o = 16; o; o >>= 1) l += __shfl_xor_sync(0xffffffffu, l, o);
    __shared__ float red[4];
    if (lane == 0) red[wid] = l;
    __syncthreads();
    if (threadIdx.x == 0) g_bsum[blockIdx.x] = red[0] + red[1] + red[2] + red[3];
}

__global__ void finalize2_kernel(float* out) {
    int lane = threadIdx.x;
    float s = g_bsum[lane] + g_bsum[lane + 32] + g_bsum[lane + 64] + g_bsum[lane + 96];
#pragma unroll
    for (int o = 16; o; o >>= 1) s += __shfl_xor_sync(0xffffffffu, s, o);
    if (lane == 0) out[0] = s * (1.0f / (float)N_ROWS);
}

// ---------------- launch ----------------
extern "C" void kernel_launch(void* const* d_in, const int* in_sizes, int n_in,
                              void* d_out, int out_size) {
    const float* z1 = (const float*)d_in[0];
    const float* z2 = (const float*)d_in[1];
    float* out = (float*)d_out;
    (void)in_sizes; (void)n_in; (void)out_size;

    cudaFuncSetAttribute(ncl_main_kernel, cudaFuncAttributeMaxDynamicSharedMemorySize, SMEM_TOTAL);

    norm_kernel<<<N_ROWS / 8, 256>>>(z1, z2);
    ncl_main_kernel<<<NCTA, 256, SMEM_TOTAL>>>();
    finalize1_kernel<<<128, 128>>>();
    finalize2_kernel<<<1, 32>>>(out);
}